// round 1
// baseline (speedup 1.0000x reference)
#include <cuda_runtime.h>

#define WS   11
#define TILE 32
#define IN   42   // TILE + WS - 1
#define NC   48   // N*C = 16*3

// ---------------- scratch (static device memory; no allocs) ----------------
__device__ float g_taps[WS];
__device__ float g_cs_sum[5][NC];
__device__ float g_ssim_sum[5][NC];

__device__ float g_x1[NC * 256 * 256];
__device__ float g_y1[NC * 256 * 256];
__device__ float g_x2[NC * 128 * 128];
__device__ float g_y2[NC * 128 * 128];
__device__ float g_x3[NC * 64 * 64];
__device__ float g_y3[NC * 64 * 64];
__device__ float g_x4[NC * 32 * 32];
__device__ float g_y4[NC * 32 * 32];

__device__ float* g_xs_tab[4] = {g_x1, g_x2, g_x3, g_x4};
__device__ float* g_ys_tab[4] = {g_y1, g_y2, g_y3, g_y4};

// ---------------- init: extract separable taps + zero accumulators ----------
__global__ void init_kernel(const float* __restrict__ win) {
    int t = threadIdx.x;
    if (t < WS) {
        // window[0,0,:,:] is outer(g,g) with sum(g)=1 -> g[i] = k[i][5]/sqrt(k[5][5])
        float center = win[5 * WS + 5];
        g_taps[t] = win[t * WS + 5] / sqrtf(center);
    }
    float* cs = &g_cs_sum[0][0];
    float* ss = &g_ssim_sum[0][0];
    for (int i = t; i < 5 * NC; i += blockDim.x) { cs[i] = 0.f; ss[i] = 0.f; }
}

// ---------------- 2x2 avg pool (all dims even at every scale) ---------------
__global__ void pool_kernel(const float* __restrict__ x0, const float* __restrict__ y0,
                            int D, int out_scale) {
    const float* xi = (out_scale == 1) ? x0 : g_xs_tab[out_scale - 2];
    const float* yi = (out_scale == 1) ? y0 : g_ys_tab[out_scale - 2];
    float* xo = g_xs_tab[out_scale - 1];
    float* yo = g_ys_tab[out_scale - 1];
    int Dh = D >> 1;
    int total = NC * Dh * Dh;
    for (int idx = blockIdx.x * blockDim.x + threadIdx.x; idx < total;
         idx += gridDim.x * blockDim.x) {
        int j  = idx % Dh;
        int t  = idx / Dh;
        int i  = t % Dh;
        int nc = t / Dh;
        size_t base = (size_t)nc * D * D + (size_t)(2 * i) * D + 2 * j;
        xo[idx] = 0.25f * (xi[base] + xi[base + 1] + xi[base + D] + xi[base + D + 1]);
        yo[idx] = 0.25f * (yi[base] + yi[base + 1] + yi[base + D] + yi[base + D + 1]);
    }
}

// ---------------- fused separable conv + SSIM/CS tile kernel ----------------
__global__ __launch_bounds__(256) void ssim_kernel(
    const float* __restrict__ x0, const float* __restrict__ y0,
    int D, int O, int scale) {
    __shared__ float2 sxy[IN][IN + 1];   // (x, y) input tile
    __shared__ float2 hA[IN][TILE];      // (hx, hy)
    __shared__ float2 hB[IN][TILE];      // (hxx, hyy)
    __shared__ float  hC[IN][TILE];      // hxy
    __shared__ float  red[16];

    const float* xb;
    const float* yb;
    if (scale == 0) { xb = x0; yb = y0; }
    else            { xb = g_xs_tab[scale - 1]; yb = g_ys_tab[scale - 1]; }

    int nc = blockIdx.z;
    xb += (size_t)nc * D * D;
    yb += (size_t)nc * D * D;

    int ox0 = blockIdx.x * TILE;
    int oy0 = blockIdx.y * TILE;
    int tid = threadIdx.y * 32 + threadIdx.x;

    float tg[WS];
#pragma unroll
    for (int k = 0; k < WS; k++) tg[k] = g_taps[k];

    // load 42x42 tile of (x,y); zero-pad out of range (outputs there are masked)
    for (int idx = tid; idx < IN * IN; idx += 256) {
        int r = idx / IN, c = idx - r * IN;
        int gy = oy0 + r, gx = ox0 + c;
        float xv = 0.f, yv = 0.f;
        if (gy < D && gx < D) {
            xv = xb[(size_t)gy * D + gx];
            yv = yb[(size_t)gy * D + gx];
        }
        sxy[r][c] = make_float2(xv, yv);
    }
    __syncthreads();

    // horizontal separable pass: 42 rows x 32 cols, 5 maps
    for (int idx = tid; idx < IN * TILE; idx += 256) {
        int r = idx >> 5, c = idx & 31;
        float hx = 0.f, hy = 0.f, hxx = 0.f, hyy = 0.f, hxy = 0.f;
#pragma unroll
        for (int k = 0; k < WS; k++) {
            float2 v = sxy[r][c + k];
            float  w = tg[k];
            float tx = w * v.x;
            float ty = w * v.y;
            hx += tx; hy += ty;
            hxx = fmaf(tx, v.x, hxx);
            hyy = fmaf(ty, v.y, hyy);
            hxy = fmaf(tx, v.y, hxy);
        }
        hA[r][c] = make_float2(hx, hy);
        hB[r][c] = make_float2(hxx, hyy);
        hC[r][c] = hxy;
    }
    __syncthreads();

    // vertical pass + SSIM epilogue: each thread does 4 output rows, 1 col
    float ssim_acc = 0.f, cs_acc = 0.f;
    int  c    = threadIdx.x;
    bool colv = (ox0 + c) < O;
#pragma unroll
    for (int rr = 0; rr < 4; rr++) {
        int r = threadIdx.y * 4 + rr;
        if (colv && (oy0 + r) < O) {
            float mx = 0.f, my = 0.f, exx = 0.f, eyy = 0.f, exy = 0.f;
#pragma unroll
            for (int k = 0; k < WS; k++) {
                float  w = tg[k];
                float2 a = hA[r + k][c];
                float2 b = hB[r + k][c];
                float  p = hC[r + k][c];
                mx  = fmaf(w, a.x, mx);
                my  = fmaf(w, a.y, my);
                exx = fmaf(w, b.x, exx);
                eyy = fmaf(w, b.y, eyy);
                exy = fmaf(w, p, exy);
            }
            float mxx = mx * mx, myy = my * my, mxy = mx * my;
            float sxx = exx - mxx, syy = eyy - myy, sxy_ = exy - mxy;
            const float C1 = 1e-4f, C2 = 9e-4f;
            float cs = __fdividef(2.f * sxy_ + C2, sxx + syy + C2);
            float ss = __fdividef(2.f * mxy + C1, mxx + myy + C1) * cs;
            cs_acc   += cs;
            ssim_acc += ss;
        }
    }

    // warp reduce + block reduce + atomic
#pragma unroll
    for (int o = 16; o > 0; o >>= 1) {
        ssim_acc += __shfl_down_sync(0xffffffffu, ssim_acc, o);
        cs_acc   += __shfl_down_sync(0xffffffffu, cs_acc, o);
    }
    if (threadIdx.x == 0) {
        red[threadIdx.y]     = ssim_acc;
        red[8 + threadIdx.y] = cs_acc;
    }
    __syncthreads();
    if (tid == 0) {
        float s = 0.f, cc = 0.f;
#pragma unroll
        for (int i = 0; i < 8; i++) { s += red[i]; cc += red[8 + i]; }
        atomicAdd(&g_ssim_sum[scale][nc], s);
        atomicAdd(&g_cs_sum[scale][nc], cc);
    }
}

// ---------------- final: relu/pow/prod over scales, mean over (n,c) ---------
__global__ void final_kernel(const float* __restrict__ weights, float* __restrict__ out) {
    __shared__ float vals[NC];
    int t = threadIdx.x;
    const int Os[5] = {502, 246, 118, 54, 22};
    if (t < NC) {
        float prod = 1.f;
#pragma unroll
        for (int s = 0; s < 5; s++) {
            float inv = 1.f / ((float)Os[s] * (float)Os[s]);
            float m = (s < 4) ? g_cs_sum[s][t] : g_ssim_sum[s][t];
            m *= inv;
            if (s < 4) m = fmaxf(m, 0.f);
            prod *= powf(m, weights[s]);
        }
        vals[t] = prod;
    }
    __syncthreads();
    if (t == 0) {
        float s = 0.f;
        for (int i = 0; i < NC; i++) s += vals[i];
        out[0] = s / (float)NC;
    }
}

// ---------------- launch --------------------------------------------------
extern "C" void kernel_launch(void* const* d_in, const int* in_sizes, int n_in,
                              void* d_out, int out_size) {
    const float* x   = (const float*)d_in[0];
    const float* y   = (const float*)d_in[1];
    const float* win = (const float*)d_in[2];
    const float* wts = (const float*)d_in[3];
    float* out = (float*)d_out;

    init_kernel<<<1, 256>>>(win);

    const int Ds[5] = {512, 256, 128, 64, 32};
    const int Os[5] = {502, 246, 118, 54, 22};

    dim3 blk(32, 8);
    for (int s = 0; s < 5; s++) {
        if (s > 0) {
            int Dh = Ds[s];
            int total = NC * Dh * Dh;
            int nb = (total + 255) / 256;
            pool_kernel<<<nb, 256>>>(x, y, Ds[s - 1], s);
        }
        int nt = (Os[s] + TILE - 1) / TILE;
        ssim_kernel<<<dim3(nt, nt, NC), blk>>>(x, y, Ds[s], Os[s], s);
    }

    final_kernel<<<1, 64>>>(wts, out);
}

// round 3
// speedup vs baseline: 1.4333x; 1.4333x over previous
#include <cuda_runtime.h>

#define WS   11
#define TILE 32
#define IN   42   // TILE + WS - 1
#define NC   48   // N*C = 16*3

// ---------------- scratch (static device memory; no allocs) ----------------
__device__ float g_taps[WS];
__device__ float g_cs_sum[5][NC];
__device__ float g_ssim_sum[5][NC];

__device__ float g_x1[NC * 256 * 256];
__device__ float g_y1[NC * 256 * 256];
__device__ float g_x2[NC * 128 * 128];
__device__ float g_y2[NC * 128 * 128];
__device__ float g_x3[NC * 64 * 64];
__device__ float g_y3[NC * 64 * 64];
__device__ float g_x4[NC * 32 * 32];
__device__ float g_y4[NC * 32 * 32];

// ============ fused pool: one block per (nc, 64x64 region) =================
__global__ __launch_bounds__(256) void pool_fused(
    const float* __restrict__ x0, const float* __restrict__ y0,
    const float* __restrict__ win) {
    __shared__ float s1x[32][33], s1y[32][33];
    __shared__ float s2x[16][17], s2y[16][17];
    __shared__ float s3x[8][9],   s3y[8][9];

    int tid = threadIdx.x;
    int b   = blockIdx.x;
    int nc  = b >> 6;
    int r   = b & 63;
    int by  = r >> 3, bx = r & 7;

    if (b == 0) {
        if (tid < WS) {
            float center = win[5 * WS + 5];
            g_taps[tid] = win[tid * WS + 5] / sqrtf(center);
        }
        float* cs = &g_cs_sum[0][0];
        float* ss = &g_ssim_sum[0][0];
        for (int i = tid; i < 5 * NC; i += 256) { cs[i] = 0.f; ss[i] = 0.f; }
    }

    const float* xin = x0 + (size_t)nc * 512 * 512;
    const float* yin = y0 + (size_t)nc * 512 * 512;

    // scale 1: 32x32 outputs from 64x64 input region
#pragma unroll
    for (int t = 0; t < 4; t++) {
        int o = tid + t * 256;
        int i = o >> 5, j = o & 31;
        int grow = by * 64 + 2 * i;
        int gcol2 = bx * 32 + j;  // float2 index
        const float2* xr0 = (const float2*)(xin + (size_t)grow * 512);
        const float2* xr1 = (const float2*)(xin + (size_t)(grow + 1) * 512);
        const float2* yr0 = (const float2*)(yin + (size_t)grow * 512);
        const float2* yr1 = (const float2*)(yin + (size_t)(grow + 1) * 512);
        float2 a = xr0[gcol2], c = xr1[gcol2];
        float2 e = yr0[gcol2], f = yr1[gcol2];
        float vx = 0.25f * ((a.x + a.y) + (c.x + c.y));
        float vy = 0.25f * ((e.x + e.y) + (f.x + f.y));
        s1x[i][j] = vx; s1y[i][j] = vy;
        size_t go = (size_t)nc * 256 * 256 + (size_t)(by * 32 + i) * 256 + (bx * 32 + j);
        g_x1[go] = vx; g_y1[go] = vy;
    }
    __syncthreads();

    // scale 2: 16x16
    {
        int i = tid >> 4, j = tid & 15;
        float vx = 0.25f * ((s1x[2*i][2*j] + s1x[2*i][2*j+1]) + (s1x[2*i+1][2*j] + s1x[2*i+1][2*j+1]));
        float vy = 0.25f * ((s1y[2*i][2*j] + s1y[2*i][2*j+1]) + (s1y[2*i+1][2*j] + s1y[2*i+1][2*j+1]));
        s2x[i][j] = vx; s2y[i][j] = vy;
        size_t go = (size_t)nc * 128 * 128 + (size_t)(by * 16 + i) * 128 + (bx * 16 + j);
        g_x2[go] = vx; g_y2[go] = vy;
    }
    __syncthreads();

    // scale 3: 8x8
    if (tid < 64) {
        int i = tid >> 3, j = tid & 7;
        float vx = 0.25f * ((s2x[2*i][2*j] + s2x[2*i][2*j+1]) + (s2x[2*i+1][2*j] + s2x[2*i+1][2*j+1]));
        float vy = 0.25f * ((s2y[2*i][2*j] + s2y[2*i][2*j+1]) + (s2y[2*i+1][2*j] + s2y[2*i+1][2*j+1]));
        s3x[i][j] = vx; s3y[i][j] = vy;
        size_t go = (size_t)nc * 64 * 64 + (size_t)(by * 8 + i) * 64 + (bx * 8 + j);
        g_x3[go] = vx; g_y3[go] = vy;
    }
    __syncthreads();

    // scale 4: 4x4
    if (tid < 16) {
        int i = tid >> 2, j = tid & 3;
        float vx = 0.25f * ((s3x[2*i][2*j] + s3x[2*i][2*j+1]) + (s3x[2*i+1][2*j] + s3x[2*i+1][2*j+1]));
        float vy = 0.25f * ((s3y[2*i][2*j] + s3y[2*i][2*j+1]) + (s3y[2*i+1][2*j] + s3y[2*i+1][2*j+1]));
        size_t go = (size_t)nc * 32 * 32 + (size_t)(by * 4 + i) * 32 + (bx * 4 + j);
        g_x4[go] = vx; g_y4[go] = vy;
    }
}

// ============ combined ssim over all scales ================================
// 4 maps: (x, y, x^2+y^2, x*y). Horizontal pass -> smem; vertical pass with
// sliding-window register reuse (4 output rows per thread, 14 row-reads).
// MUST be launched with blockDim = (32, 8).
__global__ __launch_bounds__(256) void ssim_all(
    const float* __restrict__ x0, const float* __restrict__ y0) {
    __shared__ float2 sxy[IN][IN + 1];   // (x, y)
    __shared__ float2 h1[IN][TILE];      // (hx, hy)
    __shared__ float2 h2[IN][TILE];      // (h(x^2+y^2), h(xy))
    __shared__ float  red[16];

    int b = blockIdx.x;
    const float *xb, *yb;
    int D, O, nc, bx, by, scale;
    if (b < 12288)      { scale = 0; D = 512; O = 502; int l = b;          nc = l >> 8; int r = l & 255; by = r >> 4; bx = r & 15; xb = x0;  yb = y0;  }
    else if (b < 15360) { scale = 1; D = 256; O = 246; int l = b - 12288;  nc = l >> 6; int r = l & 63;  by = r >> 3; bx = r & 7;  xb = g_x1; yb = g_y1; }
    else if (b < 16128) { scale = 2; D = 128; O = 118; int l = b - 15360;  nc = l >> 4; int r = l & 15;  by = r >> 2; bx = r & 3;  xb = g_x2; yb = g_y2; }
    else if (b < 16320) { scale = 3; D = 64;  O = 54;  int l = b - 16128;  nc = l >> 2; int r = l & 3;   by = r >> 1; bx = r & 1;  xb = g_x3; yb = g_y3; }
    else                { scale = 4; D = 32;  O = 22;  int l = b - 16320;  nc = l;      by = 0;          bx = 0;      xb = g_x4; yb = g_y4; }

    xb += (size_t)nc * D * D;
    yb += (size_t)nc * D * D;

    int ox0 = bx * TILE;
    int oy0 = by * TILE;
    int tid = threadIdx.y * 32 + threadIdx.x;

    float tg[WS];
#pragma unroll
    for (int k = 0; k < WS; k++) tg[k] = g_taps[k];

    // load 42x42 (x,y) tile; zero-pad out of range
    for (int idx = tid; idx < IN * IN; idx += 256) {
        int r = idx / IN, c = idx - r * IN;
        int gy = oy0 + r, gx = ox0 + c;
        float xv = 0.f, yv = 0.f;
        if (gy < D && gx < D) {
            xv = xb[gy * D + gx];
            yv = yb[gy * D + gx];
        }
        sxy[r][c] = make_float2(xv, yv);
    }
    __syncthreads();

    // horizontal pass: 42 rows x 32 cols, 4 maps
    for (int idx = tid; idx < IN * TILE; idx += 256) {
        int r = idx >> 5, c = idx & 31;
        float hx = 0.f, hy = 0.f, hs = 0.f, hp = 0.f;
#pragma unroll
        for (int k = 0; k < WS; k++) {
            float2 v = sxy[r][c + k];
            float  w = tg[k];
            hx = fmaf(w, v.x, hx);
            hy = fmaf(w, v.y, hy);
            float sq = fmaf(v.x, v.x, v.y * v.y);
            hs = fmaf(w, sq, hs);
            hp = fmaf(w, v.x * v.y, hp);
        }
        h1[r][c] = make_float2(hx, hy);
        h2[r][c] = make_float2(hs, hp);
    }
    __syncthreads();

    // vertical pass: each thread owns column c, 4 consecutive output rows.
    float acc[4][4];
#pragma unroll
    for (int o = 0; o < 4; o++)
#pragma unroll
        for (int m = 0; m < 4; m++) acc[o][m] = 0.f;

    int c = threadIdx.x;
    int rbase = threadIdx.y * 4;
#pragma unroll
    for (int j = 0; j < 14; j++) {
        float2 a = h1[rbase + j][c];
        float2 q = h2[rbase + j][c];
#pragma unroll
        for (int o = 0; o < 4; o++) {
            int k = j - o;
            if (k >= 0 && k < WS) {
                float w = tg[k];
                acc[o][0] = fmaf(w, a.x, acc[o][0]);
                acc[o][1] = fmaf(w, a.y, acc[o][1]);
                acc[o][2] = fmaf(w, q.x, acc[o][2]);
                acc[o][3] = fmaf(w, q.y, acc[o][3]);
            }
        }
    }

    float ssim_acc = 0.f, cs_acc = 0.f;
    bool colv = (ox0 + c) < O;
#pragma unroll
    for (int o = 0; o < 4; o++) {
        if (colv && (oy0 + rbase + o) < O) {
            float mx = acc[o][0], my = acc[o][1], ms = acc[o][2], mp = acc[o][3];
            float mxx = mx * mx, myy = my * my, mxy = mx * my;
            float svar = ms - mxx - myy;        // sigma_x^2 + sigma_y^2
            float sxy_ = mp - mxy;              // sigma_xy
            const float C1 = 1e-4f, C2 = 9e-4f;
            float cs = __fdividef(2.f * sxy_ + C2, svar + C2);
            float ss = __fdividef(2.f * mxy + C1, mxx + myy + C1) * cs;
            cs_acc   += cs;
            ssim_acc += ss;
        }
    }

    // warp reduce + block reduce + atomic
#pragma unroll
    for (int o = 16; o > 0; o >>= 1) {
        ssim_acc += __shfl_down_sync(0xffffffffu, ssim_acc, o);
        cs_acc   += __shfl_down_sync(0xffffffffu, cs_acc, o);
    }
    if (threadIdx.x == 0) {
        red[threadIdx.y]     = ssim_acc;
        red[8 + threadIdx.y] = cs_acc;
    }
    __syncthreads();
    if (tid == 0) {
        float s = 0.f, cc = 0.f;
#pragma unroll
        for (int i = 0; i < 8; i++) { s += red[i]; cc += red[8 + i]; }
        atomicAdd(&g_ssim_sum[scale][nc], s);
        atomicAdd(&g_cs_sum[scale][nc], cc);
    }
}

// ---------------- final: relu/pow/prod over scales, mean over (n,c) ---------
__global__ void final_kernel(const float* __restrict__ weights, float* __restrict__ out) {
    __shared__ float vals[NC];
    int t = threadIdx.x;
    const int Os[5] = {502, 246, 118, 54, 22};
    if (t < NC) {
        float prod = 1.f;
#pragma unroll
        for (int s = 0; s < 5; s++) {
            float inv = 1.f / ((float)Os[s] * (float)Os[s]);
            float m = (s < 4) ? g_cs_sum[s][t] : g_ssim_sum[s][t];
            m *= inv;
            if (s < 4) m = fmaxf(m, 0.f);
            prod *= powf(m, weights[s]);
        }
        vals[t] = prod;
    }
    __syncthreads();
    if (t == 0) {
        float s = 0.f;
        for (int i = 0; i < NC; i++) s += vals[i];
        out[0] = s / (float)NC;
    }
}

// ---------------- launch --------------------------------------------------
extern "C" void kernel_launch(void* const* d_in, const int* in_sizes, int n_in,
                              void* d_out, int out_size) {
    const float* x   = (const float*)d_in[0];
    const float* y   = (const float*)d_in[1];
    const float* win = (const float*)d_in[2];
    const float* wts = (const float*)d_in[3];
    float* out = (float*)d_out;

    pool_fused<<<3072, 256>>>(x, y, win);
    ssim_all<<<16368, dim3(32, 8)>>>(x, y);
    final_kernel<<<1, 64>>>(wts, out);
}

// round 4
// speedup vs baseline: 1.7389x; 1.2133x over previous
#include <cuda_runtime.h>

#define WS   11
#define TILE 32
#define IN   42
#define NC   48

typedef unsigned long long u64;

// ---------------- packed f32x2 helpers (ptxas won't auto-fuse) -------------
__device__ __forceinline__ u64 pack2(float lo, float hi) {
    u64 r; asm("mov.b64 %0, {%1, %2};" : "=l"(r) : "f"(lo), "f"(hi)); return r;
}
__device__ __forceinline__ float2 unpack2(u64 v) {
    float2 f; asm("mov.b64 {%0, %1}, %2;" : "=f"(f.x), "=f"(f.y) : "l"(v)); return f;
}
__device__ __forceinline__ u64 fma2(u64 a, u64 b, u64 c) {
    u64 d; asm("fma.rn.f32x2 %0, %1, %2, %3;" : "=l"(d) : "l"(a), "l"(b), "l"(c)); return d;
}
__device__ __forceinline__ u64 add2(u64 a, u64 b) {
    u64 d; asm("add.rn.f32x2 %0, %1, %2;" : "=l"(d) : "l"(a), "l"(b)); return d;
}
__device__ __forceinline__ u64 mul2(u64 a, u64 b) {
    u64 d; asm("mul.rn.f32x2 %0, %1, %2;" : "=l"(d) : "l"(a), "l"(b)); return d;
}

// ---------------- scratch ---------------------------------------------------
__device__ float g_cs_sum[5][NC];
__device__ float g_ssim_sum[5][NC];
__device__ u64 g_s1[NC * 256 * 256];   // interleaved (x,y)
__device__ u64 g_s2[NC * 128 * 128];
__device__ u64 g_s3[NC * 64 * 64];
__device__ u64 g_s4[NC * 32 * 32];

__global__ void init_kernel() {
    int t = threadIdx.x;
    if (t < 5 * NC) { (&g_cs_sum[0][0])[t] = 0.f; (&g_ssim_sum[0][0])[t] = 0.f; }
}

// ======== ssim core pieces (shared by both ssim kernels via macros) =========
#define SSIM_SHARED \
    __shared__ u64 sA[IN][IN + 1]; \
    __shared__ u64 h1[IN][TILE + 1]; \
    __shared__ u64 h2[IN][TILE + 1]; \
    __shared__ float tg_s[WS]; \
    __shared__ float red[16];

#define SSIM_TAPS \
    if (tid < WS) tg_s[tid] = win[tid * WS + 5] * rsqrtf(win[5 * WS + 5]);

#define SSIM_WP \
    u64 wp[WS]; \
    _Pragma("unroll") \
    for (int k = 0; k < WS; k++) { float w = tg_s[k]; wp[k] = pack2(w, w); }

#define SSIM_HORIZ \
    for (int t = tid; t < 336; t += 256) { \
        int r = t >> 3, c0 = (t & 7) * 4; \
        u64 a1[4] = {0,0,0,0}, a2[4] = {0,0,0,0}; \
        _Pragma("unroll") \
        for (int j = 0; j < 14; j++) { \
            u64 a = sA[r][c0 + j]; \
            float2 v = unpack2(a); \
            u64 q = pack2(fmaf(v.x, v.x, v.y * v.y), v.x * v.y); \
            _Pragma("unroll") \
            for (int o = 0; o < 4; o++) { \
                int k = j - o; \
                if (k >= 0 && k < WS) { \
                    a1[o] = fma2(wp[k], a, a1[o]); \
                    a2[o] = fma2(wp[k], q, a2[o]); \
                } \
            } \
        } \
        _Pragma("unroll") \
        for (int o = 0; o < 4; o++) { h1[r][c0 + o] = a1[o]; h2[r][c0 + o] = a2[o]; } \
    }

#define SSIM_VERT_AND_REDUCE(OVAL, SCALE) \
    float ssim_acc = 0.f, cs_acc = 0.f; \
    { \
        int c = threadIdx.x; \
        int rbase = threadIdx.y * 4; \
        u64 a1[4] = {0,0,0,0}, a2[4] = {0,0,0,0}; \
        _Pragma("unroll") \
        for (int j = 0; j < 14; j++) { \
            u64 a = h1[rbase + j][c]; \
            u64 q = h2[rbase + j][c]; \
            _Pragma("unroll") \
            for (int o = 0; o < 4; o++) { \
                int k = j - o; \
                if (k >= 0 && k < WS) { \
                    a1[o] = fma2(wp[k], a, a1[o]); \
                    a2[o] = fma2(wp[k], q, a2[o]); \
                } \
            } \
        } \
        bool colv = (ox0 + c) < (OVAL); \
        _Pragma("unroll") \
        for (int o = 0; o < 4; o++) { \
            if (colv && (oy0 + rbase + o) < (OVAL)) { \
                float2 m = unpack2(a1[o]); \
                float2 e = unpack2(a2[o]); \
                float mxx = m.x * m.x, myy = m.y * m.y, mxy = m.x * m.y; \
                float svar = e.x - mxx - myy; \
                float sxy_ = e.y - mxy; \
                const float C1 = 1e-4f, C2 = 9e-4f; \
                float cs = __fdividef(2.f * sxy_ + C2, svar + C2); \
                float ss = __fdividef(2.f * mxy + C1, mxx + myy + C1) * cs; \
                cs_acc += cs; ssim_acc += ss; \
            } \
        } \
    } \
    _Pragma("unroll") \
    for (int o = 16; o > 0; o >>= 1) { \
        ssim_acc += __shfl_down_sync(0xffffffffu, ssim_acc, o); \
        cs_acc   += __shfl_down_sync(0xffffffffu, cs_acc, o); \
    } \
    if (threadIdx.x == 0) { red[threadIdx.y] = ssim_acc; red[8 + threadIdx.y] = cs_acc; } \
    __syncthreads(); \
    if (tid == 0) { \
        float s = 0.f, cc = 0.f; \
        _Pragma("unroll") \
        for (int i = 0; i < 8; i++) { s += red[i]; cc += red[8 + i]; } \
        atomicAdd(&g_ssim_sum[SCALE][nc], s); \
        atomicAdd(&g_cs_sum[SCALE][nc], cc); \
    }

// ======== scale 0: ssim + pooled emission into g_s1 ========================
__global__ __launch_bounds__(256) void ssim_scale0(
    const float* __restrict__ x0, const float* __restrict__ y0,
    const float* __restrict__ win) {
    SSIM_SHARED
    int b = blockIdx.x;
    int nc = b >> 8;
    int r0 = b & 255;
    int by = r0 >> 4, bx = r0 & 15;
    const float* xb = x0 + (size_t)nc * 262144;
    const float* yb = y0 + (size_t)nc * 262144;
    int ox0 = bx * 32, oy0 = by * 32;
    int tid = threadIdx.y * 32 + threadIdx.x;

    SSIM_TAPS

    for (int idx = tid; idx < IN * IN; idx += 256) {
        int r = idx / IN, c = idx - r * IN;
        int gy = oy0 + r, gx = ox0 + c;
        float xv = 0.f, yv = 0.f;
        if (gy < 512 && gx < 512) { xv = xb[gy * 512 + gx]; yv = yb[gy * 512 + gx]; }
        sA[r][c] = pack2(xv, yv);
    }
    __syncthreads();

    SSIM_WP
    SSIM_HORIZ

    // pooled emission: owned 32x32 -> 16x16 of scale-1 (reads sA, no sync hazard)
    {
        int i = tid >> 4, j = tid & 15;
        u64 s = add2(add2(sA[2*i][2*j], sA[2*i][2*j+1]),
                     add2(sA[2*i+1][2*j], sA[2*i+1][2*j+1]));
        s = mul2(s, pack2(0.25f, 0.25f));
        g_s1[(size_t)nc * 65536 + (size_t)(by * 16 + i) * 256 + (bx * 16 + j)] = s;
    }
    __syncthreads();

    SSIM_VERT_AND_REDUCE(502, 0)
}

// ======== scales 1-4 ========================================================
__global__ __launch_bounds__(256) void ssim_rest(const float* __restrict__ win) {
    SSIM_SHARED
    int b = blockIdx.x;
    int D, O, nc, bx, by, scale;
    const u64* src;
    if (b < 3072)      { scale = 1; D = 256; O = 246; int l = b;        nc = l >> 6; int r = l & 63; by = r >> 3; bx = r & 7; src = g_s1; }
    else if (b < 3840) { scale = 2; D = 128; O = 118; int l = b - 3072; nc = l >> 4; int r = l & 15; by = r >> 2; bx = r & 3; src = g_s2; }
    else if (b < 4032) { scale = 3; D = 64;  O = 54;  int l = b - 3840; nc = l >> 2; int r = l & 3;  by = r >> 1; bx = r & 1; src = g_s3; }
    else               { scale = 4; D = 32;  O = 22;  int l = b - 4032; nc = l;      by = 0;         bx = 0;      src = g_s4; }
    src += (size_t)nc * D * D;
    int ox0 = bx * 32, oy0 = by * 32;
    int tid = threadIdx.y * 32 + threadIdx.x;

    SSIM_TAPS

    for (int idx = tid; idx < IN * IN; idx += 256) {
        int r = idx / IN, c = idx - r * IN;
        int gy = oy0 + r, gx = ox0 + c;
        sA[r][c] = (gy < D && gx < D) ? src[gy * D + gx] : 0ull;
    }
    __syncthreads();

    SSIM_WP
    SSIM_HORIZ
    __syncthreads();

    SSIM_VERT_AND_REDUCE(O, scale)
}

// ======== pool chain: s1 -> s2,s3,s4 ========================================
__global__ __launch_bounds__(256) void pool_rest() {
    __shared__ u64 s2s[32][33];
    __shared__ u64 s3s[16][17];
    int tid = threadIdx.x;
    int b = blockIdx.x;
    int nc = b >> 4;
    int r = b & 15;
    int by = r >> 2, bx = r & 3;
    const u64* s1 = g_s1 + (size_t)nc * 65536;
    u64 quarter = pack2(0.25f, 0.25f);
#pragma unroll
    for (int t = 0; t < 4; t++) {
        int o = tid + t * 256;
        int i = o >> 5, j = o & 31;
        int gr = by * 64 + 2 * i, gc = bx * 64 + 2 * j;
        u64 v = mul2(add2(add2(s1[gr * 256 + gc], s1[gr * 256 + gc + 1]),
                          add2(s1[(gr + 1) * 256 + gc], s1[(gr + 1) * 256 + gc + 1])), quarter);
        s2s[i][j] = v;
        g_s2[(size_t)nc * 16384 + (size_t)(by * 32 + i) * 128 + (bx * 32 + j)] = v;
    }
    __syncthreads();
    {
        int i = tid >> 4, j = tid & 15;
        u64 v = mul2(add2(add2(s2s[2*i][2*j], s2s[2*i][2*j+1]),
                          add2(s2s[2*i+1][2*j], s2s[2*i+1][2*j+1])), quarter);
        s3s[i][j] = v;
        g_s3[(size_t)nc * 4096 + (size_t)(by * 16 + i) * 64 + (bx * 16 + j)] = v;
    }
    __syncthreads();
    if (tid < 64) {
        int i = tid >> 3, j = tid & 7;
        u64 v = mul2(add2(add2(s3s[2*i][2*j], s3s[2*i][2*j+1]),
                          add2(s3s[2*i+1][2*j], s3s[2*i+1][2*j+1])), quarter);
        g_s4[(size_t)nc * 1024 + (size_t)(by * 8 + i) * 32 + (bx * 8 + j)] = v;
    }
}

// ---------------- final ------------------------------------------------------
__global__ void final_kernel(const float* __restrict__ weights, float* __restrict__ out) {
    __shared__ float vals[NC];
    int t = threadIdx.x;
    const int Os[5] = {502, 246, 118, 54, 22};
    if (t < NC) {
        float prod = 1.f;
#pragma unroll
        for (int s = 0; s < 5; s++) {
            float inv = 1.f / ((float)Os[s] * (float)Os[s]);
            float m = (s < 4) ? g_cs_sum[s][t] : g_ssim_sum[s][t];
            m *= inv;
            if (s < 4) m = fmaxf(m, 0.f);
            prod *= powf(m, weights[s]);
        }
        vals[t] = prod;
    }
    __syncthreads();
    if (t == 0) {
        float s = 0.f;
        for (int i = 0; i < NC; i++) s += vals[i];
        out[0] = s / (float)NC;
    }
}

// ---------------- launch -----------------------------------------------------
extern "C" void kernel_launch(void* const* d_in, const int* in_sizes, int n_in,
                              void* d_out, int out_size) {
    const float* x   = (const float*)d_in[0];
    const float* y   = (const float*)d_in[1];
    const float* win = (const float*)d_in[2];
    const float* wts = (const float*)d_in[3];
    float* out = (float*)d_out;

    init_kernel<<<1, 256>>>();
    ssim_scale0<<<12288, dim3(32, 8)>>>(x, y, win);
    pool_rest<<<768, 256>>>();
    ssim_rest<<<4080, dim3(32, 8)>>>(win);
    final_kernel<<<1, 64>>>(wts, out);
}